// round 17
// baseline (speedup 1.0000x reference)
#include <cuda_runtime.h>
#include <cuda_bf16.h>

// Problem constants
#define BB 4
#define PP 64
#define SS 8
#define YD 16
#define GD 48
#define NOUT (BB*PP*PP*SS*SS)          // 1,048,576 outputs

#define WARPS_PER_BLOCK 8              // 256 threads = 256 consecutive outputs

__device__ __forceinline__ float dot4(float4 v, float4 w) {
    return fmaf(v.x, w.x, fmaf(v.y, w.y, fmaf(v.z, w.z, v.w * w.w)));
}

// Proven R2/R13 streaming schedule for one 6KB tile (32 outputs).
// 2 batches x 6 coalesced LDG.128; weight column f%12 = (lane%12+8k)%12
// cycles {A,B,C}; per-lane partial -> conflict-free STS.32; lane r reduces
// its 12 partials via 3 conflict-free LDS.128.
__device__ __forceinline__ float stream_tile(const float4* __restrict__ gs,
                                             float* __restrict__ p, int lane,
                                             float4 wA, float4 wB, float4 wC) {
    float4 v0 = __ldcs(gs + lane +   0);
    float4 v1 = __ldcs(gs + lane +  32);
    float4 v2 = __ldcs(gs + lane +  64);
    float4 v3 = __ldcs(gs + lane +  96);
    float4 v4 = __ldcs(gs + lane + 128);
    float4 v5 = __ldcs(gs + lane + 160);
    p[lane +   0] = dot4(v0, wA);
    p[lane +  32] = dot4(v1, wB);
    p[lane +  64] = dot4(v2, wC);
    p[lane +  96] = dot4(v3, wA);
    p[lane + 128] = dot4(v4, wB);
    p[lane + 160] = dot4(v5, wC);

    float4 u0 = __ldcs(gs + lane + 192);
    float4 u1 = __ldcs(gs + lane + 224);
    float4 u2 = __ldcs(gs + lane + 256);
    float4 u3 = __ldcs(gs + lane + 288);
    float4 u4 = __ldcs(gs + lane + 320);
    float4 u5 = __ldcs(gs + lane + 352);
    p[lane + 192] = dot4(u0, wA);
    p[lane + 224] = dot4(u1, wB);
    p[lane + 256] = dot4(u2, wC);
    p[lane + 288] = dot4(u3, wA);
    p[lane + 320] = dot4(u4, wB);
    p[lane + 352] = dot4(u5, wC);

    __syncwarp();

    const float4* pr = (const float4*)(p + lane * 12);   // 48B aligned
    float4 t0 = pr[0], t1 = pr[1], t2 = pr[2];
    return ((t0.x + t0.y) + (t0.z + t0.w))
         + ((t1.x + t1.y) + (t1.z + t1.w))
         + ((t2.x + t2.y) + (t2.z + t2.w));
}

// ---------------------------------------------------------------------------
// Fused kernel, producer/consumer named barrier. Block = 256 consecutive
// outputs: (b,i) fixed, j spans 4 values.
//
//   warp 0 (producer): builds sc1[4][8] (+bias) and sc2[8] leanly
//     (5 iters x one quarter-dot4/lane, quad shuffle-fold, ~12 live regs,
//      strictly before its own g loads), bar.arrive 0,256 (NON-blocking),
//     then streams its tile.
//   warps 1..7 (consumers): stream immediately (no prologue, no stall),
//     bar.sync 0,256 right before the table read — warp 0 arrived ~1000cyc
//     earlier, so the barrier releases instantly.
//
// 32 arrives + 224 syncs = 256: canonical producer pattern on barrier 0.
// __launch_bounds__(256, 7): proven 36-reg ceiling for this hot loop.
// ---------------------------------------------------------------------------
__global__ __launch_bounds__(32 * WARPS_PER_BLOCK, 7)
void fused_kernel(const float* __restrict__ y,
                  const float* __restrict__ g,
                  const float* __restrict__ Wy,
                  const float* __restrict__ by,
                  const float* __restrict__ Wg,
                  const float* __restrict__ bg,
                  float* __restrict__ out) {
    __shared__ float part[WARPS_PER_BLOCK][12 * 32];
    __shared__ float sc1[4 * SS];      // c1[jj][s] (+bias)
    __shared__ float sc2[SS];          // c2[s]

    const int tid  = threadIdx.x;
    const int lane = tid & 31;
    const int wIn  = tid >> 5;
    const int blockBase = blockIdx.x * 256;

    // ---- per-lane weight columns: (lane%12 + {0,8,4}) % 12 ----
    const int l12 = lane % 12;
    int cBi = l12 + 8; if (cBi >= 12) cBi -= 12;
    int cCi = l12 + 4; if (cCi >= 12) cCi -= 12;
    const float4* wv = (const float4*)Wg;
    const float4 wA = __ldg(wv + l12);
    const float4 wB = __ldg(wv + cBi);
    const float4 wC = __ldg(wv + cCi);

    const int base = blockBase + wIn * 32;
    const float4* gs = (const float4*)(g + (size_t)base * GD);
    float* p = part[wIn];

    float sum;
    if (wIn == 0) {
        // ---- producer: lean table build (strictly before warp 0's loads) ----
        const int b  =  blockBase >> 18;
        const int i  = (blockBase >> 12) & 63;
        const int j0 = (blockBase >> 6)  & 63;       // low 2 bits are 0
        const float bias = __ldg(by) + __ldg(bg);
#pragma unroll
        for (int r = 0; r < 5; ++r) {
            const int t = lane + 32 * r;             // 0..159
            const int e = t >> 2;                    // table entry 0..39
            const int q = t & 3;                     // quarter of the 16-dot
            int row, woff;
            if (e < 32) { row = ((b << 6) + j0 + (e >> 3)) * SS + (e & 7); woff = 0; }
            else        { row = ((b << 6) + i) * SS + (e - 32);            woff = YD; }
            float4 yv = __ldg((const float4*)(y + (size_t)row * YD) + q);
            float4 wq = __ldg((const float4*)(Wy + woff) + q);
            float d = dot4(yv, wq);
            d += __shfl_xor_sync(0xffffffffu, d, 1);
            d += __shfl_xor_sync(0xffffffffu, d, 2);
            if (q == 0) {
                if (e < 32) sc1[e] = d + bias;
                else        sc2[e - 32] = d;
            }
        }
        __syncwarp();                                // own-warp smem visibility
        asm volatile("bar.arrive 0, 256;" ::: "memory");   // non-blocking
        sum = stream_tile(gs, p, lane, wA, wB, wC);
    } else {
        // ---- consumers: stream with zero prologue ----
        sum = stream_tile(gs, p, lane, wA, wB, wC);
        asm volatile("bar.sync 0, 256;" ::: "memory");     // ~instant release
    }

    // broadcast terms: warp's jj = wIn>>1, si0 = (wIn&1)*4
    sum += sc1[((wIn >> 1) << 3) + (lane & 7)];
    sum += sc2[((wIn & 1) << 2) + (lane >> 3)];

    __stcs(out + base + lane, sum);
}

// ---------------------------------------------------------------------------
// Launch
// inputs (metadata order): y(32768), pairwise_g(50331648), Wy(32), by(1),
//                          Wg(48), bg(1)
// ---------------------------------------------------------------------------
extern "C" void kernel_launch(void* const* d_in, const int* in_sizes, int n_in,
                              void* d_out, int out_size) {
    const float* y  = (const float*)d_in[0];
    const float* g  = (const float*)d_in[1];
    const float* Wy = (const float*)d_in[2];
    const float* by = (const float*)d_in[3];
    const float* Wg = (const float*)d_in[4];
    const float* bg = (const float*)d_in[5];
    float* out = (float*)d_out;

    const int blocks = NOUT / 256;                // 4096
    fused_kernel<<<blocks, 32 * WARPS_PER_BLOCK>>>(y, g, Wy, by, Wg, bg, out);
}